// round 7
// baseline (speedup 1.0000x reference)
#include <cuda_runtime.h>
#include <cuda_bf16.h>
#include <math.h>
#include <stdint.h>

// Problem constants
#define BATCH 8
#define T_SEQ 1024
#define C_EMB 768
#define NH    8
#define HD    96
#define M_ROWS (BATCH * T_SEQ)   // 8192
#define GK    768

// ---------------------------------------------------------------------------
// Scratch
// ---------------------------------------------------------------------------
__device__ float g_qkv[(size_t)M_ROWS * 3 * C_EMB];
__device__ float g_att[(size_t)M_ROWS * C_EMB];

// ---------------------------------------------------------------------------
// PTX helpers (baseline ISA, ok at compute_103)
// ---------------------------------------------------------------------------
__device__ __forceinline__ uint32_t smem_u32(const void* p) {
    uint32_t a;
    asm("{ .reg .u64 t; cvta.to.shared.u64 t, %1; cvt.u32.u64 %0, t; }"
        : "=r"(a) : "l"(p));
    return a;
}
__device__ __forceinline__ void mma_bf16(
    float& c0, float& c1, float& c2, float& c3,
    uint32_t a0, uint32_t a1, uint32_t a2, uint32_t a3,
    uint32_t b0, uint32_t b1)
{
    asm volatile(
        "mma.sync.aligned.m16n8k16.row.col.f32.bf16.bf16.f32 "
        "{%0,%1,%2,%3}, {%4,%5,%6,%7}, {%8,%9}, {%0,%1,%2,%3};"
        : "+f"(c0), "+f"(c1), "+f"(c2), "+f"(c3)
        : "r"(a0), "r"(a1), "r"(a2), "r"(a3), "r"(b0), "r"(b1));
}
__device__ __forceinline__ void ldm_x4(
    uint32_t& r0, uint32_t& r1, uint32_t& r2, uint32_t& r3, uint32_t saddr)
{
    asm volatile("ldmatrix.sync.aligned.m8n8.x4.shared.b16 {%0,%1,%2,%3}, [%4];"
        : "=r"(r0), "=r"(r1), "=r"(r2), "=r"(r3) : "r"(saddr));
}

__device__ __forceinline__ uint32_t pkbf(__nv_bfloat16 a, __nv_bfloat16 b) {
    __nv_bfloat162 t(a, b);
    return *reinterpret_cast<uint32_t*>(&t);
}
__device__ __forceinline__ uint32_t pkf2(float a, float b) {
    __nv_bfloat162 t = __float22bfloat162_rn(make_float2(a, b));
    return *reinterpret_cast<uint32_t*>(&t);
}
__device__ __forceinline__ uint32_t pksplit(float a, float b, uint32_t& lo) {
    __nv_bfloat16 ha = __float2bfloat16_rn(a);
    __nv_bfloat16 hb = __float2bfloat16_rn(b);
    lo = pkf2(a - __bfloat162float(ha), b - __bfloat162float(hb));
    return pkbf(ha, hb);
}

// ---------------------------------------------------------------------------
// Split-bf16 tensor-core GEMM, ldmatrix fragment loads.
//   C[m][n] = sum_k A[m][k]*W[n][k] + bias[n]; D = Ah*Bh + Ah*Bl + Al*Bh
// CTA 64x128 (4 warps, warp 64x32), K chunked 32, double-buffered smem.
// ---------------------------------------------------------------------------
#define AS_STRIDE 40
#define ABUF (64 * AS_STRIDE)
#define BBUF (128 * AS_STRIDE)
#define BUFSZ (2 * ABUF + 2 * BBUF)
#define GEMM_SMEM_BYTES (2 * BUFSZ * 2)
#define NCHUNK (GK / 32)

__global__ __launch_bounds__(128, 3) void gemm_mma(
    const float* __restrict__ A, const float* __restrict__ W,
    const float* __restrict__ bias, float* __restrict__ C, int N)
{
    extern __shared__ __nv_bfloat16 smb[];

    const int tid  = threadIdx.x;
    const int w    = tid >> 5;
    const int lane = tid & 31;
    const int gr   = lane >> 2;
    const int lc   = lane & 3;
    const int bm   = blockIdx.y * 64;
    const int bn   = blockIdx.x * 128;

    // ldmatrix per-lane byte offsets (relative to tile base)
    const uint32_t smbase = smem_u32(smb);
    const uint32_t aoff = (((lane & 15) * AS_STRIDE) + ((lane >> 4) << 3)) * 2;
    const uint32_t boff = (((w * 32) + ((lane >> 4) << 3) + (lane & 7)) * AS_STRIDE) * 2
                          + ((lane >> 3) & 1) * 16;

    float acc[4][4][4];
#pragma unroll
    for (int mt = 0; mt < 4; mt++)
#pragma unroll
        for (int nt = 0; nt < 4; nt++)
#pragma unroll
            for (int r = 0; r < 4; r++) acc[mt][nt][r] = 0.f;

    {
        __nv_bfloat16* Ah = smb;
        __nv_bfloat16* Al = Ah + ABUF;
        __nv_bfloat16* Bh = Al + ABUF;
        __nv_bfloat16* Bl = Bh + BBUF;
#pragma unroll
        for (int j = 0; j < 4; j++) {
            int i = tid + 128 * j;
            int r = i >> 3, c4 = (i & 7) * 4;
            float4 v = *(const float4*)(A + (size_t)(bm + r) * GK + c4);
            uint32_t lx, ly;
            uint32_t hx = pksplit(v.x, v.y, lx);
            uint32_t hy = pksplit(v.z, v.w, ly);
            int idx = r * AS_STRIDE + c4;
            *(uint2*)&Ah[idx] = make_uint2(hx, hy);
            *(uint2*)&Al[idx] = make_uint2(lx, ly);
        }
#pragma unroll
        for (int j = 0; j < 8; j++) {
            int i = tid + 128 * j;
            int r = i >> 3, c4 = (i & 7) * 4;
            float4 v = *(const float4*)(W + (size_t)(bn + r) * GK + c4);
            uint32_t lx, ly;
            uint32_t hx = pksplit(v.x, v.y, lx);
            uint32_t hy = pksplit(v.z, v.w, ly);
            int idx = r * AS_STRIDE + c4;
            *(uint2*)&Bh[idx] = make_uint2(hx, hy);
            *(uint2*)&Bl[idx] = make_uint2(lx, ly);
        }
    }
    __syncthreads();

    float4 pa[4], pb[8];
    for (int t = 0; t < NCHUNK; t++) {
        const bool more = (t + 1) < NCHUNK;
        if (more) {
            const int k0 = (t + 1) * 32;
#pragma unroll
            for (int j = 0; j < 4; j++) {
                int i = tid + 128 * j;
                int r = i >> 3, c4 = (i & 7) * 4;
                pa[j] = *(const float4*)(A + (size_t)(bm + r) * GK + k0 + c4);
            }
#pragma unroll
            for (int j = 0; j < 8; j++) {
                int i = tid + 128 * j;
                int r = i >> 3, c4 = (i & 7) * 4;
                pb[j] = *(const float4*)(W + (size_t)(bn + r) * GK + k0 + c4);
            }
        }

        {
            const uint32_t bufb = smbase + (uint32_t)((t & 1) * (BUFSZ * 2));
            const uint32_t ah_b = bufb + aoff;
            const uint32_t al_b = ah_b + ABUF * 2;
            const uint32_t bh_b = bufb + (2 * ABUF) * 2 + boff;
            const uint32_t bl_b = bh_b + BBUF * 2;

#pragma unroll
            for (int ks = 0; ks < 2; ks++) {
                const uint32_t kbb = (uint32_t)(ks * 32);   // 16 bf16 = 32 bytes
                uint32_t af[4][4], bhf[4][2], blf[4][2];
#pragma unroll
                for (int mt = 0; mt < 4; mt++)
                    ldm_x4(af[mt][0], af[mt][1], af[mt][2], af[mt][3],
                           ah_b + (uint32_t)(mt * 16 * AS_STRIDE * 2) + kbb);
#pragma unroll
                for (int p = 0; p < 2; p++) {
                    uint32_t base = (uint32_t)(p * 16 * AS_STRIDE * 2) + kbb;
                    ldm_x4(bhf[2 * p][0], bhf[2 * p][1], bhf[2 * p + 1][0], bhf[2 * p + 1][1],
                           bh_b + base);
                    ldm_x4(blf[2 * p][0], blf[2 * p][1], blf[2 * p + 1][0], blf[2 * p + 1][1],
                           bl_b + base);
                }
#pragma unroll
                for (int mt = 0; mt < 4; mt++)
#pragma unroll
                    for (int nt = 0; nt < 4; nt++) {
                        mma_bf16(acc[mt][nt][0], acc[mt][nt][1],
                                 acc[mt][nt][2], acc[mt][nt][3],
                                 af[mt][0], af[mt][1], af[mt][2], af[mt][3],
                                 bhf[nt][0], bhf[nt][1]);
                        mma_bf16(acc[mt][nt][0], acc[mt][nt][1],
                                 acc[mt][nt][2], acc[mt][nt][3],
                                 af[mt][0], af[mt][1], af[mt][2], af[mt][3],
                                 blf[nt][0], blf[nt][1]);
                    }
#pragma unroll
                for (int mt = 0; mt < 4; mt++)
                    ldm_x4(af[mt][0], af[mt][1], af[mt][2], af[mt][3],
                           al_b + (uint32_t)(mt * 16 * AS_STRIDE * 2) + kbb);
#pragma unroll
                for (int mt = 0; mt < 4; mt++)
#pragma unroll
                    for (int nt = 0; nt < 4; nt++)
                        mma_bf16(acc[mt][nt][0], acc[mt][nt][1],
                                 acc[mt][nt][2], acc[mt][nt][3],
                                 af[mt][0], af[mt][1], af[mt][2], af[mt][3],
                                 bhf[nt][0], bhf[nt][1]);
            }
        }

        if (more) {
            __nv_bfloat16* buf = smb + ((t + 1) & 1) * BUFSZ;
            __nv_bfloat16* Ah = buf;
            __nv_bfloat16* Al = Ah + ABUF;
            __nv_bfloat16* Bh = Al + ABUF;
            __nv_bfloat16* Bl = Bh + BBUF;
#pragma unroll
            for (int j = 0; j < 4; j++) {
                int i = tid + 128 * j;
                int r = i >> 3, c4 = (i & 7) * 4;
                float4 v = pa[j];
                uint32_t lx, ly;
                uint32_t hx = pksplit(v.x, v.y, lx);
                uint32_t hy = pksplit(v.z, v.w, ly);
                int idx = r * AS_STRIDE + c4;
                *(uint2*)&Ah[idx] = make_uint2(hx, hy);
                *(uint2*)&Al[idx] = make_uint2(lx, ly);
            }
#pragma unroll
            for (int j = 0; j < 8; j++) {
                int i = tid + 128 * j;
                int r = i >> 3, c4 = (i & 7) * 4;
                float4 v = pb[j];
                uint32_t lx, ly;
                uint32_t hx = pksplit(v.x, v.y, lx);
                uint32_t hy = pksplit(v.z, v.w, ly);
                int idx = r * AS_STRIDE + c4;
                *(uint2*)&Bh[idx] = make_uint2(hx, hy);
                *(uint2*)&Bl[idx] = make_uint2(lx, ly);
            }
        }
        __syncthreads();
    }

#pragma unroll
    for (int nt = 0; nt < 4; nt++) {
        const int col = bn + w * 32 + nt * 8 + lc * 2;
        const float2 bj = *(const float2*)(bias + col);
#pragma unroll
        for (int mt = 0; mt < 4; mt++) {
            const int row0 = bm + mt * 16 + gr;
            float2 v0, v1;
            v0.x = acc[mt][nt][0] + bj.x; v0.y = acc[mt][nt][1] + bj.y;
            v1.x = acc[mt][nt][2] + bj.x; v1.y = acc[mt][nt][3] + bj.y;
            *(float2*)(C + (size_t)row0 * N + col) = v0;
            *(float2*)(C + (size_t)(row0 + 8) * N + col) = v1;
        }
    }
}

// ---------------------------------------------------------------------------
// Flash attention on mma.sync, split-bf16 both phases, ldmatrix B-frag loads.
// ---------------------------------------------------------------------------
#define KST 104
#define VST 72
#define FL_KL_OFF (64 * KST)
#define FL_VT_OFF (2 * 64 * KST)
#define FL_VTL_OFF (FL_VT_OFF + 96 * VST)
#define FL_SMEM_BF16 (2 * 64 * KST + 2 * 96 * VST)
#define FL_SMEM_BYTES (FL_SMEM_BF16 * 2)   // 54272

__global__ __launch_bounds__(128, 2) void flash_mma(
    const float* __restrict__ qkv, float* __restrict__ out)
{
    extern __shared__ char fsm[];
    __nv_bfloat16* Kh  = (__nv_bfloat16*)fsm;
    __nv_bfloat16* Kl  = Kh + FL_KL_OFF;
    __nv_bfloat16* Vth = Kh + FL_VT_OFF;
    __nv_bfloat16* Vtl = Kh + FL_VTL_OFF;
    float* Qs = (float*)fsm;               // overlays K region, pre-loop only

    const int qt = 15 - (int)blockIdx.x;
    const int h  = blockIdx.y;
    const int b  = blockIdx.z;
    const int tid  = threadIdx.x;
    const int w    = tid >> 5;
    const int lane = tid & 31;
    const int gr   = lane >> 2;
    const int lc   = lane & 3;
    const int r0l  = w * 16 + gr;
    const int r1l  = r0l + 8;

    // ldmatrix per-lane byte offsets
    const uint32_t smbase = smem_u32(fsm);
    const uint32_t rowsel = (uint32_t)(((lane >> 4) << 3) + (lane & 7));
    const uint32_t colsel = (uint32_t)(((lane >> 3) & 1) * 16);
    const uint32_t kh_b  = smbase + rowsel * (KST * 2) + colsel;
    const uint32_t kl_b  = kh_b + FL_KL_OFF * 2;
    const uint32_t vth_b = smbase + FL_VT_OFF * 2 + rowsel * (VST * 2) + colsel;
    const uint32_t vtl_b = vth_b + 96 * VST * 2;

    const float rscale = 0.10206207261596577f;  // 1/sqrt(96)

    // ---- stage Q (scaled), extract split A-fragments ----
    const float* qbase = qkv + (size_t)(b * T_SEQ + qt * 64) * 3 * C_EMB + h * HD;
#pragma unroll
    for (int it = 0; it < 12; it++) {
        int idx = tid + 128 * it;
        int r = idx / 24, c4 = (idx % 24) * 4;
        float4 v = *(const float4*)(qbase + (size_t)r * 3 * C_EMB + c4);
        v.x *= rscale; v.y *= rscale; v.z *= rscale; v.w *= rscale;
        *(float4*)&Qs[r * 100 + c4] = v;
    }
    __syncthreads();

    uint32_t Qhf[6][4], Qlf[6][4];
#pragma unroll
    for (int ks = 0; ks < 6; ks++) {
        const int kb = ks * 16 + 2 * lc;
#pragma unroll
        for (int f = 0; f < 4; f++) {
            const int rr = (f & 1) ? r1l : r0l;
            const int kk = kb + ((f >> 1) ? 8 : 0);
            Qhf[ks][f] = pksplit(Qs[rr * 100 + kk], Qs[rr * 100 + kk + 1], Qlf[ks][f]);
        }
    }
    __syncthreads();

    float accO[12][4];
#pragma unroll
    for (int nt = 0; nt < 12; nt++)
#pragma unroll
        for (int r = 0; r < 4; r++) accO[nt][r] = 0.f;
    float m0 = -1e30f, m1 = -1e30f, l0 = 0.f, l1 = 0.f;

    for (int kt = 0; kt <= qt; kt++) {
        const float* kb_ = qkv + (size_t)(b * T_SEQ + kt * 64) * 3 * C_EMB + C_EMB + h * HD;
        const float* vb_ = kb_ + C_EMB;

        // K tile split hi/lo
#pragma unroll
        for (int it = 0; it < 12; it++) {
            int idx = tid + 128 * it;
            int r = idx / 24, c4 = (idx % 24) * 4;
            float4 v = *(const float4*)(kb_ + (size_t)r * 3 * C_EMB + c4);
            uint32_t lx, ly;
            uint32_t hx = pksplit(v.x, v.y, lx);
            uint32_t hy = pksplit(v.z, v.w, ly);
            int sidx = r * KST + c4;
            *(uint2*)&Kh[sidx] = make_uint2(hx, hy);
            *(uint2*)&Kl[sidx] = make_uint2(lx, ly);
        }
        // V transposed [d][tok], split hi/lo
#pragma unroll
        for (int it = 0; it < 6; it++) {
            int idx = tid + 128 * it;
            int t2 = idx & 31, d4 = (idx >> 5) * 4;
            float4 v0 = *(const float4*)(vb_ + (size_t)(2 * t2) * 3 * C_EMB + d4);
            float4 v1 = *(const float4*)(vb_ + (size_t)(2 * t2 + 1) * 3 * C_EMB + d4);
            uint32_t lo;
#pragma unroll
            for (int c = 0; c < 4; c++) {
                float a = (&v0.x)[c], bb = (&v1.x)[c];
                uint32_t hi = pksplit(a, bb, lo);
                *(uint32_t*)&Vth[(d4 + c) * VST + 2 * t2] = hi;
                *(uint32_t*)&Vtl[(d4 + c) * VST + 2 * t2] = lo;
            }
        }
        __syncthreads();

        // ---- S = Q K^T (3-product split) ----
        float accS[8][4];
#pragma unroll
        for (int nt = 0; nt < 8; nt++)
#pragma unroll
            for (int r = 0; r < 4; r++) accS[nt][r] = 0.f;

#pragma unroll
        for (int ks = 0; ks < 6; ks++) {
            const uint32_t kxb = (uint32_t)(ks * 32);
            uint32_t bh[8][2], bl[8][2];
#pragma unroll
            for (int p = 0; p < 4; p++) {
                uint32_t off = (uint32_t)(p * 16 * KST * 2) + kxb;
                ldm_x4(bh[2 * p][0], bh[2 * p][1], bh[2 * p + 1][0], bh[2 * p + 1][1],
                       kh_b + off);
                ldm_x4(bl[2 * p][0], bl[2 * p][1], bl[2 * p + 1][0], bl[2 * p + 1][1],
                       kl_b + off);
            }
#pragma unroll
            for (int nt = 0; nt < 8; nt++) {
                mma_bf16(accS[nt][0], accS[nt][1], accS[nt][2], accS[nt][3],
                         Qhf[ks][0], Qhf[ks][1], Qhf[ks][2], Qhf[ks][3],
                         bh[nt][0], bh[nt][1]);
                mma_bf16(accS[nt][0], accS[nt][1], accS[nt][2], accS[nt][3],
                         Qhf[ks][0], Qhf[ks][1], Qhf[ks][2], Qhf[ks][3],
                         bl[nt][0], bl[nt][1]);
                mma_bf16(accS[nt][0], accS[nt][1], accS[nt][2], accS[nt][3],
                         Qlf[ks][0], Qlf[ks][1], Qlf[ks][2], Qlf[ks][3],
                         bh[nt][0], bh[nt][1]);
            }
        }

        // ---- causal mask on diagonal tile ----
        if (kt == qt) {
#pragma unroll
            for (int nt = 0; nt < 8; nt++) {
                int c0 = nt * 8 + 2 * lc, c1 = c0 + 1;
                if (c0 > r0l) accS[nt][0] = -1e30f;
                if (c1 > r0l) accS[nt][1] = -1e30f;
                if (c0 > r1l) accS[nt][2] = -1e30f;
                if (c1 > r1l) accS[nt][3] = -1e30f;
            }
        }

        // ---- online softmax ----
        float mx0 = accS[0][0], mx1 = accS[0][2];
#pragma unroll
        for (int nt = 0; nt < 8; nt++) {
            mx0 = fmaxf(mx0, fmaxf(accS[nt][0], accS[nt][1]));
            mx1 = fmaxf(mx1, fmaxf(accS[nt][2], accS[nt][3]));
        }
        mx0 = fmaxf(mx0, __shfl_xor_sync(0xffffffffu, mx0, 1));
        mx0 = fmaxf(mx0, __shfl_xor_sync(0xffffffffu, mx0, 2));
        mx1 = fmaxf(mx1, __shfl_xor_sync(0xffffffffu, mx1, 1));
        mx1 = fmaxf(mx1, __shfl_xor_sync(0xffffffffu, mx1, 2));
        float nm0 = fmaxf(m0, mx0), nm1 = fmaxf(m1, mx1);
        float corr0 = __expf(m0 - nm0), corr1 = __expf(m1 - nm1);
        m0 = nm0; m1 = nm1;

        float rs0 = 0.f, rs1 = 0.f;
        uint32_t aPh[4][4], aPl[4][4];
#pragma unroll
        for (int nt = 0; nt < 8; nt++) {
            float p0 = __expf(accS[nt][0] - m0);
            float p1 = __expf(accS[nt][1] - m0);
            float p2 = __expf(accS[nt][2] - m1);
            float p3 = __expf(accS[nt][3] - m1);
            rs0 += p0 + p1; rs1 += p2 + p3;
            const int i0 = (nt & 1) * 2;
            aPh[nt >> 1][i0 + 0] = pksplit(p0, p1, aPl[nt >> 1][i0 + 0]);
            aPh[nt >> 1][i0 + 1] = pksplit(p2, p3, aPl[nt >> 1][i0 + 1]);
        }
        rs0 += __shfl_xor_sync(0xffffffffu, rs0, 1);
        rs0 += __shfl_xor_sync(0xffffffffu, rs0, 2);
        rs1 += __shfl_xor_sync(0xffffffffu, rs1, 1);
        rs1 += __shfl_xor_sync(0xffffffffu, rs1, 2);
        l0 = l0 * corr0 + rs0;
        l1 = l1 * corr1 + rs1;

#pragma unroll
        for (int nt = 0; nt < 12; nt++) {
            accO[nt][0] *= corr0; accO[nt][1] *= corr0;
            accO[nt][2] *= corr1; accO[nt][3] *= corr1;
        }

        // ---- O += P V (3-product split), ldmatrix V-frags ----
#pragma unroll
        for (int kt2 = 0; kt2 < 4; kt2++) {
            const uint32_t kxb = (uint32_t)(kt2 * 32);
            uint32_t a0 = aPh[kt2][0], a1 = aPh[kt2][1], a2 = aPh[kt2][2], a3 = aPh[kt2][3];
            uint32_t c0 = aPl[kt2][0], c1 = aPl[kt2][1], c2 = aPl[kt2][2], c3 = aPl[kt2][3];
#pragma unroll
            for (int p = 0; p < 6; p++) {
                uint32_t off = (uint32_t)(p * 16 * VST * 2) + kxb;
                uint32_t bh0, bh1, bh2, bh3, bl0, bl1, bl2, bl3;
                ldm_x4(bh0, bh1, bh2, bh3, vth_b + off);
                ldm_x4(bl0, bl1, bl2, bl3, vtl_b + off);
                const int n0 = 2 * p, n1 = 2 * p + 1;
                mma_bf16(accO[n0][0], accO[n0][1], accO[n0][2], accO[n0][3],
                         a0, a1, a2, a3, bh0, bh1);
                mma_bf16(accO[n0][0], accO[n0][1], accO[n0][2], accO[n0][3],
                         a0, a1, a2, a3, bl0, bl1);
                mma_bf16(accO[n0][0], accO[n0][1], accO[n0][2], accO[n0][3],
                         c0, c1, c2, c3, bh0, bh1);
                mma_bf16(accO[n1][0], accO[n1][1], accO[n1][2], accO[n1][3],
                         a0, a1, a2, a3, bh2, bh3);
                mma_bf16(accO[n1][0], accO[n1][1], accO[n1][2], accO[n1][3],
                         a0, a1, a2, a3, bl2, bl3);
                mma_bf16(accO[n1][0], accO[n1][1], accO[n1][2], accO[n1][3],
                         c0, c1, c2, c3, bh2, bh3);
            }
        }
        __syncthreads();
    }

    // ---- epilogue ----
    const float inv0 = 1.f / l0;
    const float inv1 = 1.f / l1;
    const size_t grow0 = (size_t)(b * T_SEQ + qt * 64 + r0l);
    const size_t grow1 = grow0 + 8;
#pragma unroll
    for (int nt = 0; nt < 12; nt++) {
        const int col = h * HD + nt * 8 + 2 * lc;
        float2 v0, v1;
        v0.x = accO[nt][0] * inv0; v0.y = accO[nt][1] * inv0;
        v1.x = accO[nt][2] * inv1; v1.y = accO[nt][3] * inv1;
        *(float2*)(out + grow0 * C_EMB + col) = v0;
        *(float2*)(out + grow1 * C_EMB + col) = v1;
    }
}

// ---------------------------------------------------------------------------
// Launch
// ---------------------------------------------------------------------------
extern "C" void kernel_launch(void* const* d_in, const int* in_sizes, int n_in,
                              void* d_out, int out_size)
{
    (void)in_sizes; (void)n_in; (void)out_size;
    const float* x  = (const float*)d_in[0];
    const float* w1 = (const float*)d_in[1];
    const float* b1 = (const float*)d_in[2];
    const float* w2 = (const float*)d_in[3];
    const float* b2 = (const float*)d_in[4];
    float* out = (float*)d_out;

    float *qkv = nullptr, *att = nullptr;
    cudaGetSymbolAddress((void**)&qkv, g_qkv);
    cudaGetSymbolAddress((void**)&att, g_att);

    cudaFuncSetAttribute(gemm_mma,
                         cudaFuncAttributeMaxDynamicSharedMemorySize,
                         GEMM_SMEM_BYTES);
    cudaFuncSetAttribute(flash_mma,
                         cudaFuncAttributeMaxDynamicSharedMemorySize,
                         FL_SMEM_BYTES);

    // QKV projection: 8192 x 2304 x 768
    gemm_mma<<<dim3(3 * C_EMB / 128, M_ROWS / 64), 128, GEMM_SMEM_BYTES>>>(
        x, w1, b1, qkv, 3 * C_EMB);

    // Causal attention
    flash_mma<<<dim3(T_SEQ / 64, NH, BATCH), 128, FL_SMEM_BYTES>>>(qkv, att);

    // Output projection: 8192 x 768 x 768
    gemm_mma<<<dim3(C_EMB / 128, M_ROWS / 64), 128, GEMM_SMEM_BYTES>>>(
        att, w2, b2, out, C_EMB);
}

// round 8
// speedup vs baseline: 1.0989x; 1.0989x over previous
#include <cuda_runtime.h>
#include <cuda_bf16.h>
#include <math.h>
#include <stdint.h>

// Problem constants
#define BATCH 8
#define T_SEQ 1024
#define C_EMB 768
#define NH    8
#define HD    96
#define M_ROWS (BATCH * T_SEQ)   // 8192
#define GK    768

// ---------------------------------------------------------------------------
// Scratch: pre-split bf16 hi/lo arrays
// ---------------------------------------------------------------------------
__device__ __nv_bfloat16 g_xh[(size_t)M_ROWS * C_EMB];
__device__ __nv_bfloat16 g_xl[(size_t)M_ROWS * C_EMB];
__device__ __nv_bfloat16 g_w1h[(size_t)3 * C_EMB * C_EMB];
__device__ __nv_bfloat16 g_w1l[(size_t)3 * C_EMB * C_EMB];
__device__ __nv_bfloat16 g_w2h[(size_t)C_EMB * C_EMB];
__device__ __nv_bfloat16 g_w2l[(size_t)C_EMB * C_EMB];
__device__ __nv_bfloat16 g_qkvh[(size_t)M_ROWS * 3 * C_EMB];
__device__ __nv_bfloat16 g_qkvl[(size_t)M_ROWS * 3 * C_EMB];
__device__ __nv_bfloat16 g_atth[(size_t)M_ROWS * C_EMB];
__device__ __nv_bfloat16 g_attl[(size_t)M_ROWS * C_EMB];

// ---------------------------------------------------------------------------
// PTX helpers (baseline ISA at compute_103)
// ---------------------------------------------------------------------------
__device__ __forceinline__ uint32_t smem_u32(const void* p) {
    uint32_t a;
    asm("{ .reg .u64 t; cvta.to.shared.u64 t, %1; cvt.u32.u64 %0, t; }"
        : "=r"(a) : "l"(p));
    return a;
}
__device__ __forceinline__ void mma_bf16(
    float& c0, float& c1, float& c2, float& c3,
    uint32_t a0, uint32_t a1, uint32_t a2, uint32_t a3,
    uint32_t b0, uint32_t b1)
{
    asm volatile(
        "mma.sync.aligned.m16n8k16.row.col.f32.bf16.bf16.f32 "
        "{%0,%1,%2,%3}, {%4,%5,%6,%7}, {%8,%9}, {%0,%1,%2,%3};"
        : "+f"(c0), "+f"(c1), "+f"(c2), "+f"(c3)
        : "r"(a0), "r"(a1), "r"(a2), "r"(a3), "r"(b0), "r"(b1));
}
__device__ __forceinline__ void ldm_x4(
    uint32_t& r0, uint32_t& r1, uint32_t& r2, uint32_t& r3, uint32_t saddr)
{
    asm volatile("ldmatrix.sync.aligned.m8n8.x4.shared.b16 {%0,%1,%2,%3}, [%4];"
        : "=r"(r0), "=r"(r1), "=r"(r2), "=r"(r3) : "r"(saddr));
}
__device__ __forceinline__ void ldm_x4_t(
    uint32_t& r0, uint32_t& r1, uint32_t& r2, uint32_t& r3, uint32_t saddr)
{
    asm volatile("ldmatrix.sync.aligned.m8n8.x4.trans.shared.b16 {%0,%1,%2,%3}, [%4];"
        : "=r"(r0), "=r"(r1), "=r"(r2), "=r"(r3) : "r"(saddr));
}
__device__ __forceinline__ void cp16(uint32_t dst, const void* src) {
    asm volatile("cp.async.cg.shared.global [%0], [%1], 16;"
        :: "r"(dst), "l"(src) : "memory");
}
#define CP_COMMIT() asm volatile("cp.async.commit_group;" ::: "memory")
#define CP_WAIT0()  asm volatile("cp.async.wait_group 0;" ::: "memory")
#define CP_WAIT1()  asm volatile("cp.async.wait_group 1;" ::: "memory")

__device__ __forceinline__ uint32_t pkbf(__nv_bfloat16 a, __nv_bfloat16 b) {
    __nv_bfloat162 t(a, b);
    return *reinterpret_cast<uint32_t*>(&t);
}
__device__ __forceinline__ uint32_t pkf2(float a, float b) {
    __nv_bfloat162 t = __float22bfloat162_rn(make_float2(a, b));
    return *reinterpret_cast<uint32_t*>(&t);
}
__device__ __forceinline__ uint32_t pksplit(float a, float b, uint32_t& lo) {
    __nv_bfloat16 ha = __float2bfloat16_rn(a);
    __nv_bfloat16 hb = __float2bfloat16_rn(b);
    lo = pkf2(a - __bfloat162float(ha), b - __bfloat162float(hb));
    return pkbf(ha, hb);
}

// ---------------------------------------------------------------------------
// Pre-split fp32 -> bf16 hi/lo (elementwise)
// ---------------------------------------------------------------------------
__global__ void split_f32(const float* __restrict__ s,
                          __nv_bfloat16* __restrict__ h,
                          __nv_bfloat16* __restrict__ l, int n4)
{
    int i = blockIdx.x * blockDim.x + threadIdx.x;
    int stride = gridDim.x * blockDim.x;
    for (; i < n4; i += stride) {
        float4 v = ((const float4*)s)[i];
        uint32_t l0, l1;
        uint32_t h0 = pksplit(v.x, v.y, l0);
        uint32_t h1 = pksplit(v.z, v.w, l1);
        ((uint2*)h)[i] = make_uint2(h0, h1);
        ((uint2*)l)[i] = make_uint2(l0, l1);
    }
}

// ---------------------------------------------------------------------------
// Split-bf16 GEMM on pre-split inputs, cp.async double-buffered.
//   C = A * W^T + bias;  D = Ah*Bh + Ah*Bl + Al*Bh
// CTA 64x128 (128 thr, 4 warps each 64x32), K chunked 32.
// SPLIT_OUT: write bf16 hi/lo pair arrays instead of fp32.
// ---------------------------------------------------------------------------
#define AS_STRIDE 40
#define ABUF (64 * AS_STRIDE)
#define BBUF (128 * AS_STRIDE)
#define BUFSZ (2 * ABUF + 2 * BBUF)          // bf16 elems per stage
#define GEMM_SMEM_BYTES (2 * BUFSZ * 2)
#define NCHUNK (GK / 32)

template <bool SPLIT_OUT>
__global__ __launch_bounds__(128, 3) void gemm_mma(
    const __nv_bfloat16* __restrict__ Ahg, const __nv_bfloat16* __restrict__ Alg,
    const __nv_bfloat16* __restrict__ Bhg, const __nv_bfloat16* __restrict__ Blg,
    const float* __restrict__ bias,
    float* __restrict__ Cf,
    __nv_bfloat16* __restrict__ Ch, __nv_bfloat16* __restrict__ Cl,
    int N)
{
    extern __shared__ __nv_bfloat16 smb[];

    const int tid  = threadIdx.x;
    const int w    = tid >> 5;
    const int lane = tid & 31;
    const int gr   = lane >> 2;
    const int lc   = lane & 3;
    const int bm   = blockIdx.y * 64;
    const int bn   = blockIdx.x * 128;

    const uint32_t smbase = smem_u32(smb);
    const uint32_t aoff = (((lane & 15) * AS_STRIDE) + ((lane >> 4) << 3)) * 2;
    const uint32_t boff = (((w * 32) + ((lane >> 4) << 3) + (lane & 7)) * AS_STRIDE) * 2
                          + ((lane >> 3) & 1) * 16;

    // cp.async loader indices
    const int ar = tid >> 2, ack = tid & 3;          // A: rows 0..31 (+32), 4 chunks
    // per chunk: A 64 rows x 4 chunks (hi+lo), B 128 rows x 4 chunks (hi+lo)

    auto issue_chunk = [&](int t, int buf) {
        const uint32_t bb = smbase + (uint32_t)(buf * (BUFSZ * 2));
        const int k0 = t * 32;
#pragma unroll
        for (int j = 0; j < 2; j++) {
            int r = ar + 32 * j;
            const size_t so = (size_t)(bm + r) * GK + k0 + ack * 8;
            uint32_t d = bb + (uint32_t)(r * 80 + ack * 16);
            cp16(d, Ahg + so);
            cp16(d + ABUF * 2, Alg + so);
        }
#pragma unroll
        for (int j = 0; j < 4; j++) {
            int r = ar + 32 * j;
            const size_t so = (size_t)(bn + r) * GK + k0 + ack * 8;
            uint32_t d = bb + (uint32_t)(2 * ABUF * 2 + r * 80 + ack * 16);
            cp16(d, Bhg + so);
            cp16(d + BBUF * 2, Blg + so);
        }
        CP_COMMIT();
    };

    float acc[4][4][4];
#pragma unroll
    for (int mt = 0; mt < 4; mt++)
#pragma unroll
        for (int nt = 0; nt < 4; nt++)
#pragma unroll
            for (int r = 0; r < 4; r++) acc[mt][nt][r] = 0.f;

    issue_chunk(0, 0);
    issue_chunk(1, 1);

    for (int t = 0; t < NCHUNK; t++) {
        if (t + 1 < NCHUNK) { CP_WAIT1(); } else { CP_WAIT0(); }
        __syncthreads();

        {
            const uint32_t bufb = smbase + (uint32_t)((t & 1) * (BUFSZ * 2));
            const uint32_t ah_b = bufb + aoff;
            const uint32_t al_b = ah_b + ABUF * 2;
            const uint32_t bh_b = bufb + (2 * ABUF) * 2 + boff;
            const uint32_t bl_b = bh_b + BBUF * 2;

#pragma unroll
            for (int ks = 0; ks < 2; ks++) {
                const uint32_t kbb = (uint32_t)(ks * 32);
                uint32_t af[4][4], bhf[4][2], blf[4][2];
#pragma unroll
                for (int mt = 0; mt < 4; mt++)
                    ldm_x4(af[mt][0], af[mt][1], af[mt][2], af[mt][3],
                           ah_b + (uint32_t)(mt * 16 * AS_STRIDE * 2) + kbb);
#pragma unroll
                for (int p = 0; p < 2; p++) {
                    uint32_t base = (uint32_t)(p * 16 * AS_STRIDE * 2) + kbb;
                    ldm_x4(bhf[2 * p][0], bhf[2 * p][1], bhf[2 * p + 1][0], bhf[2 * p + 1][1],
                           bh_b + base);
                    ldm_x4(blf[2 * p][0], blf[2 * p][1], blf[2 * p + 1][0], blf[2 * p + 1][1],
                           bl_b + base);
                }
#pragma unroll
                for (int mt = 0; mt < 4; mt++)
#pragma unroll
                    for (int nt = 0; nt < 4; nt++) {
                        mma_bf16(acc[mt][nt][0], acc[mt][nt][1],
                                 acc[mt][nt][2], acc[mt][nt][3],
                                 af[mt][0], af[mt][1], af[mt][2], af[mt][3],
                                 bhf[nt][0], bhf[nt][1]);
                        mma_bf16(acc[mt][nt][0], acc[mt][nt][1],
                                 acc[mt][nt][2], acc[mt][nt][3],
                                 af[mt][0], af[mt][1], af[mt][2], af[mt][3],
                                 blf[nt][0], blf[nt][1]);
                    }
#pragma unroll
                for (int mt = 0; mt < 4; mt++)
                    ldm_x4(af[mt][0], af[mt][1], af[mt][2], af[mt][3],
                           al_b + (uint32_t)(mt * 16 * AS_STRIDE * 2) + kbb);
#pragma unroll
                for (int mt = 0; mt < 4; mt++)
#pragma unroll
                    for (int nt = 0; nt < 4; nt++)
                        mma_bf16(acc[mt][nt][0], acc[mt][nt][1],
                                 acc[mt][nt][2], acc[mt][nt][3],
                                 af[mt][0], af[mt][1], af[mt][2], af[mt][3],
                                 bhf[nt][0], bhf[nt][1]);
            }
        }
        __syncthreads();
        if (t + 2 < NCHUNK) issue_chunk(t + 2, t & 1);
    }

    // epilogue
#pragma unroll
    for (int nt = 0; nt < 4; nt++) {
        const int col = bn + w * 32 + nt * 8 + lc * 2;
        const float2 bj = *(const float2*)(bias + col);
#pragma unroll
        for (int mt = 0; mt < 4; mt++) {
            const int row0 = bm + mt * 16 + gr;
            float x0 = acc[mt][nt][0] + bj.x, y0 = acc[mt][nt][1] + bj.y;
            float x1 = acc[mt][nt][2] + bj.x, y1 = acc[mt][nt][3] + bj.y;
            if (SPLIT_OUT) {
                uint32_t lo0, lo1;
                uint32_t hi0 = pksplit(x0, y0, lo0);
                uint32_t hi1 = pksplit(x1, y1, lo1);
                *(uint32_t*)(Ch + (size_t)row0 * N + col) = hi0;
                *(uint32_t*)(Cl + (size_t)row0 * N + col) = lo0;
                *(uint32_t*)(Ch + (size_t)(row0 + 8) * N + col) = hi1;
                *(uint32_t*)(Cl + (size_t)(row0 + 8) * N + col) = lo1;
            } else {
                *(float2*)(Cf + (size_t)row0 * N + col) = make_float2(x0, y0);
                *(float2*)(Cf + (size_t)(row0 + 8) * N + col) = make_float2(x1, y1);
            }
        }
    }
}

// ---------------------------------------------------------------------------
// Flash attention, BQ=128, 256 threads (8 warps x 16 q-rows).
// All operands pre-split bf16 (from gemm1). cp.async double-buffered K/V.
// V kept row-major [tok][d]; PV B-frags via ldmatrix.trans.
// Scale 1/sqrt(d) applied to fp32 S after QK mma.
// ---------------------------------------------------------------------------
#define FKST 104                      // row stride in bf16 (208 B)
#define FBUF_B (64 * FKST * 2)        // 13312 B per array per stage
#define FBUF_TOTAL (4 * FBUF_B)       // Kh,Kl,Vh,Vl = 53248 B
#define FL_SMEM_BYTES (2 * FBUF_TOTAL) // 106496

__global__ __launch_bounds__(256, 1) void flash_mma(
    const __nv_bfloat16* __restrict__ qkvh,
    const __nv_bfloat16* __restrict__ qkvl,
    __nv_bfloat16* __restrict__ atth,
    __nv_bfloat16* __restrict__ attl)
{
    extern __shared__ char fsm[];
    const uint32_t smbase = smem_u32(fsm);

    const int qtp = 7 - (int)blockIdx.x;   // heavy tiles first
    const int h   = blockIdx.y;
    const int b   = blockIdx.z;
    const int tid  = threadIdx.x;
    const int w    = tid >> 5;             // 0..7
    const int lane = tid & 31;
    const int gr   = lane >> 2;
    const int lc   = lane & 3;
    const int r0l  = w * 16 + gr;          // local q row A (0..119)
    const int r1l  = r0l + 8;

    const int nkt = 2 * qtp + 2;
    const float rscale = 0.10206207261596577f;

    // cp.async loader: 4 arrays x 64 rows x 12 chunks(16B) = 3072 / 256 thr
    auto issue_tile = [&](int kt, int buf) {
        const uint32_t bb = smbase + (uint32_t)(buf * FBUF_TOTAL);
        const size_t rowbase = (size_t)(b * T_SEQ + kt * 64);
        const size_t koff = (size_t)C_EMB + h * HD;
        const size_t voff = (size_t)2 * C_EMB + h * HD;
#pragma unroll
        for (int j = 0; j < 3; j++) {
            int i = tid + 256 * j;
            int r = i / 12, ck = i % 12;
            const size_t so = (rowbase + r) * (3 * C_EMB) + ck * 8;
            uint32_t d = bb + (uint32_t)(r * 208 + ck * 16);
            cp16(d, qkvh + so + koff);                    // Kh
            cp16(d + FBUF_B, qkvl + so + koff);           // Kl
            cp16(d + 2 * FBUF_B, qkvh + so + voff);       // Vh
            cp16(d + 3 * FBUF_B, qkvl + so + voff);       // Vl
        }
        CP_COMMIT();
    };

    // preload tile 0 into buf0 (async) while staging Q into buf1
    issue_tile(0, 0);

    {   // stage Q (bf16 hi/lo) into buf1 region: Qh at +0, Ql at +26624
        const uint32_t qb = smbase + FBUF_TOTAL;
        const size_t rowbase = (size_t)(b * T_SEQ + qtp * 128);
        const size_t qoff = (size_t)h * HD;
#pragma unroll
        for (int j = 0; j < 6; j++) {
            int i = tid + 256 * j;
            int r = i / 12, ck = i % 12;
            const size_t so = (rowbase + r) * (3 * C_EMB) + qoff + ck * 8;
            uint32_t d = qb + (uint32_t)(r * 208 + ck * 16);
            *(uint4*)(fsm + (d - smbase)) = *(const uint4*)(qkvh + so);
            *(uint4*)(fsm + (d - smbase) + 26624) = *(const uint4*)(qkvl + so);
        }
    }
    __syncthreads();

    // extract Q A-fragments
    uint32_t Qhf[6][4], Qlf[6][4];
    {
        const uint32_t afl = (uint32_t)((lane & 15) * 208 + ((lane >> 4) << 4));
        const uint32_t qh_b = smbase + FBUF_TOTAL + (uint32_t)(w * 16 * 208) + afl;
#pragma unroll
        for (int ks = 0; ks < 6; ks++) {
            ldm_x4(Qhf[ks][0], Qhf[ks][1], Qhf[ks][2], Qhf[ks][3], qh_b + ks * 32);
            ldm_x4(Qlf[ks][0], Qlf[ks][1], Qlf[ks][2], Qlf[ks][3], qh_b + 26624 + ks * 32);
        }
    }
    __syncthreads();   // everyone done with buf1 before tile1 lands there
    issue_tile(1, 1);

    // fragment address components
    const uint32_t kfl = (uint32_t)((((lane >> 4) << 3) + (lane & 7)) * 208
                                    + ((lane >> 3) & 1) * 16);
    const uint32_t vfl = (uint32_t)((lane & 15) * 208 + ((lane >> 4) << 4));

    float accO[12][4];
#pragma unroll
    for (int nt = 0; nt < 12; nt++)
#pragma unroll
        for (int r = 0; r < 4; r++) accO[nt][r] = 0.f;
    float m0 = -1e30f, m1 = -1e30f, l0 = 0.f, l1 = 0.f;

    for (int kt = 0; kt < nkt; kt++) {
        if (kt + 1 < nkt) { CP_WAIT1(); } else { CP_WAIT0(); }
        __syncthreads();

        const uint32_t bb = smbase + (uint32_t)((kt & 1) * FBUF_TOTAL);
        const uint32_t kh_b = bb + kfl;
        const uint32_t kl_b = kh_b + FBUF_B;
        const uint32_t vh_b = bb + 2 * FBUF_B + vfl;
        const uint32_t vl_b = vh_b + FBUF_B;

        // ---- S = Q K^T ----
        float accS[8][4];
#pragma unroll
        for (int nt = 0; nt < 8; nt++)
#pragma unroll
            for (int r = 0; r < 4; r++) accS[nt][r] = 0.f;

#pragma unroll
        for (int ks = 0; ks < 6; ks++) {
            const uint32_t kxb = (uint32_t)(ks * 32);
            uint32_t bh[8][2], bl[8][2];
#pragma unroll
            for (int p = 0; p < 4; p++) {
                uint32_t off = (uint32_t)(p * 16 * 208) + kxb;
                ldm_x4(bh[2 * p][0], bh[2 * p][1], bh[2 * p + 1][0], bh[2 * p + 1][1],
                       kh_b + off);
                ldm_x4(bl[2 * p][0], bl[2 * p][1], bl[2 * p + 1][0], bl[2 * p + 1][1],
                       kl_b + off);
            }
#pragma unroll
            for (int nt = 0; nt < 8; nt++) {
                mma_bf16(accS[nt][0], accS[nt][1], accS[nt][2], accS[nt][3],
                         Qhf[ks][0], Qhf[ks][1], Qhf[ks][2], Qhf[ks][3],
                         bh[nt][0], bh[nt][1]);
                mma_bf16(accS[nt][0], accS[nt][1], accS[nt][2], accS[nt][3],
                         Qhf[ks][0], Qhf[ks][1], Qhf[ks][2], Qhf[ks][3],
                         bl[nt][0], bl[nt][1]);
                mma_bf16(accS[nt][0], accS[nt][1], accS[nt][2], accS[nt][3],
                         Qlf[ks][0], Qlf[ks][1], Qlf[ks][2], Qlf[ks][3],
                         bh[nt][0], bh[nt][1]);
            }
        }

        // scale (1/sqrt d) + causal mask
#pragma unroll
        for (int nt = 0; nt < 8; nt++)
#pragma unroll
            for (int r = 0; r < 4; r++) accS[nt][r] *= rscale;

        if (kt >= 2 * qtp) {
            const int qg0 = qtp * 128 + r0l;
            const int qg1 = qg0 + 8;
#pragma unroll
            for (int nt = 0; nt < 8; nt++) {
                int c0 = kt * 64 + nt * 8 + 2 * lc, c1 = c0 + 1;
                if (c0 > qg0) accS[nt][0] = -1e30f;
                if (c1 > qg0) accS[nt][1] = -1e30f;
                if (c0 > qg1) accS[nt][2] = -1e30f;
                if (c1 > qg1) accS[nt][3] = -1e30f;
            }
        }

        // ---- online softmax ----
        float mx0 = accS[0][0], mx1 = accS[0][2];
#pragma unroll
        for (int nt = 0; nt < 8; nt++) {
            mx0 = fmaxf(mx0, fmaxf(accS[nt][0], accS[nt][1]));
            mx1 = fmaxf(mx1, fmaxf(accS[nt][2], accS[nt][3]));
        }
        mx0 = fmaxf(mx0, __shfl_xor_sync(0xffffffffu, mx0, 1));
        mx0 = fmaxf(mx0, __shfl_xor_sync(0xffffffffu, mx0, 2));
        mx1 = fmaxf(mx1, __shfl_xor_sync(0xffffffffu, mx1, 1));
        mx1 = fmaxf(mx1, __shfl_xor_sync(0xffffffffu, mx1, 2));
        float nm0 = fmaxf(m0, mx0), nm1 = fmaxf(m1, mx1);
        float corr0 = __expf(m0 - nm0), corr1 = __expf(m1 - nm1);
        m0 = nm0; m1 = nm1;

        float rs0 = 0.f, rs1 = 0.f;
        uint32_t aPh[4][4], aPl[4][4];
#pragma unroll
        for (int nt = 0; nt < 8; nt++) {
            float p0 = __expf(accS[nt][0] - m0);
            float p1 = __expf(accS[nt][1] - m0);
            float p2 = __expf(accS[nt][2] - m1);
            float p3 = __expf(accS[nt][3] - m1);
            rs0 += p0 + p1; rs1 += p2 + p3;
            const int i0 = (nt & 1) * 2;
            aPh[nt >> 1][i0 + 0] = pksplit(p0, p1, aPl[nt >> 1][i0 + 0]);
            aPh[nt >> 1][i0 + 1] = pksplit(p2, p3, aPl[nt >> 1][i0 + 1]);
        }
        rs0 += __shfl_xor_sync(0xffffffffu, rs0, 1);
        rs0 += __shfl_xor_sync(0xffffffffu, rs0, 2);
        rs1 += __shfl_xor_sync(0xffffffffu, rs1, 1);
        rs1 += __shfl_xor_sync(0xffffffffu, rs1, 2);
        l0 = l0 * corr0 + rs0;
        l1 = l1 * corr1 + rs1;

#pragma unroll
        for (int nt = 0; nt < 12; nt++) {
            accO[nt][0] *= corr0; accO[nt][1] *= corr0;
            accO[nt][2] *= corr1; accO[nt][3] *= corr1;
        }

        // ---- O += P V : V row-major, ldmatrix.trans B-frags ----
#pragma unroll
        for (int kt2 = 0; kt2 < 4; kt2++) {
            const uint32_t toff = (uint32_t)(kt2 * 16 * 208);
            uint32_t a0 = aPh[kt2][0], a1 = aPh[kt2][1], a2 = aPh[kt2][2], a3 = aPh[kt2][3];
            uint32_t c0 = aPl[kt2][0], c1 = aPl[kt2][1], c2 = aPl[kt2][2], c3 = aPl[kt2][3];
#pragma unroll
            for (int p = 0; p < 6; p++) {
                const uint32_t off = toff + (uint32_t)(p * 32);
                uint32_t bh0, bh1, bh2, bh3, bl0, bl1, bl2, bl3;
                ldm_x4_t(bh0, bh1, bh2, bh3, vh_b + off);
                ldm_x4_t(bl0, bl1, bl2, bl3, vl_b + off);
                const int n0 = 2 * p, n1 = 2 * p + 1;
                mma_bf16(accO[n0][0], accO[n0][1], accO[n0][2], accO[n0][3],
                         a0, a1, a2, a3, bh0, bh1);
                mma_bf16(accO[n0][0], accO[n0][1], accO[n0][2], accO[n0][3],
                         a0, a1, a2, a3, bl0, bl1);
                mma_bf16(accO[n0][0], accO[n0][1], accO[n0][2], accO[n0][3],
                         c0, c1, c2, c3, bh0, bh1);
                mma_bf16(accO[n1][0], accO[n1][1], accO[n1][2], accO[n1][3],
                         a0, a1, a2, a3, bh2, bh3);
                mma_bf16(accO[n1][0], accO[n1][1], accO[n1][2], accO[n1][3],
                         a0, a1, a2, a3, bl2, bl3);
                mma_bf16(accO[n1][0], accO[n1][1], accO[n1][2], accO[n1][3],
                         c0, c1, c2, c3, bh2, bh3);
            }
        }
        __syncthreads();
        if (kt + 2 < nkt) issue_tile(kt + 2, kt & 1);
    }

    // ---- epilogue: write split att ----
    const float inv0 = 1.f / l0;
    const float inv1 = 1.f / l1;
    const size_t grow0 = (size_t)(b * T_SEQ + qtp * 128 + r0l);
    const size_t grow1 = grow0 + 8;
#pragma unroll
    for (int nt = 0; nt < 12; nt++) {
        const int col = h * HD + nt * 8 + 2 * lc;
        uint32_t lo0, lo1;
        uint32_t hi0 = pksplit(accO[nt][0] * inv0, accO[nt][1] * inv0, lo0);
        uint32_t hi1 = pksplit(accO[nt][2] * inv1, accO[nt][3] * inv1, lo1);
        *(uint32_t*)(atth + grow0 * C_EMB + col) = hi0;
        *(uint32_t*)(attl + grow0 * C_EMB + col) = lo0;
        *(uint32_t*)(atth + grow1 * C_EMB + col) = hi1;
        *(uint32_t*)(attl + grow1 * C_EMB + col) = lo1;
    }
}

// ---------------------------------------------------------------------------
// Launch
// ---------------------------------------------------------------------------
extern "C" void kernel_launch(void* const* d_in, const int* in_sizes, int n_in,
                              void* d_out, int out_size)
{
    (void)in_sizes; (void)n_in; (void)out_size;
    const float* x  = (const float*)d_in[0];
    const float* w1 = (const float*)d_in[1];
    const float* b1 = (const float*)d_in[2];
    const float* w2 = (const float*)d_in[3];
    const float* b2 = (const float*)d_in[4];
    float* out = (float*)d_out;

    __nv_bfloat16 *xh, *xl, *w1h, *w1l, *w2h, *w2l, *qh, *ql, *ah, *al;
    cudaGetSymbolAddress((void**)&xh, g_xh);
    cudaGetSymbolAddress((void**)&xl, g_xl);
    cudaGetSymbolAddress((void**)&w1h, g_w1h);
    cudaGetSymbolAddress((void**)&w1l, g_w1l);
    cudaGetSymbolAddress((void**)&w2h, g_w2h);
    cudaGetSymbolAddress((void**)&w2l, g_w2l);
    cudaGetSymbolAddress((void**)&qh, g_qkvh);
    cudaGetSymbolAddress((void**)&ql, g_qkvl);
    cudaGetSymbolAddress((void**)&ah, g_atth);
    cudaGetSymbolAddress((void**)&al, g_attl);

    cudaFuncSetAttribute(gemm_mma<true>,
                         cudaFuncAttributeMaxDynamicSharedMemorySize, GEMM_SMEM_BYTES);
    cudaFuncSetAttribute(gemm_mma<false>,
                         cudaFuncAttributeMaxDynamicSharedMemorySize, GEMM_SMEM_BYTES);
    cudaFuncSetAttribute(flash_mma,
                         cudaFuncAttributeMaxDynamicSharedMemorySize, FL_SMEM_BYTES);

    // pre-split inputs
    split_f32<<<256, 256>>>(x,  xh,  xl,  M_ROWS * C_EMB / 4);
    split_f32<<<256, 256>>>(w1, w1h, w1l, 3 * C_EMB * C_EMB / 4);
    split_f32<<<64,  256>>>(w2, w2h, w2l, C_EMB * C_EMB / 4);

    // QKV projection -> split qkv
    gemm_mma<true><<<dim3(3 * C_EMB / 128, M_ROWS / 64), 128, GEMM_SMEM_BYTES>>>(
        xh, xl, w1h, w1l, b1, nullptr, qh, ql, 3 * C_EMB);

    // Causal attention -> split att
    flash_mma<<<dim3(T_SEQ / 128, NH, BATCH), 256, FL_SMEM_BYTES>>>(qh, ql, ah, al);

    // Output projection -> fp32 out
    gemm_mma<false><<<dim3(C_EMB / 128, M_ROWS / 64), 128, GEMM_SMEM_BYTES>>>(
        ah, al, w2h, w2l, b2, out, nullptr, nullptr, C_EMB);
}